// round 2
// baseline (speedup 1.0000x reference)
#include <cuda_runtime.h>
#include <math.h>

#define T_   16
#define B_   8
#define H_   224
#define W_   224
#define C_   3
#define CH_  32
#define OUT_ 10
#define NIMG (T_*B_)     // 128
#define KX   113         // W/2+1

typedef unsigned long long ull;

// ---- packed f32x2 helpers (sm_100a FFMA2 path; ptxas won't auto-fuse) ----
__device__ __forceinline__ ull pack2(float lo, float hi) {
    ull r;
    asm("mov.b64 %0, {%1, %2};" : "=l"(r) : "f"(lo), "f"(hi));
    return r;
}
__device__ __forceinline__ void unpack2(ull v, float& lo, float& hi) {
    asm("mov.b64 {%0, %1}, %2;" : "=f"(lo), "=f"(hi) : "l"(v));
}
__device__ __forceinline__ ull fma2(ull a, ull b, ull c) {
    ull d;
    asm("fma.rn.f32x2 %0, %1, %2, %3;" : "=l"(d) : "l"(a), "l"(b), "l"(c));
    return d;
}

// ---- scratch (static device arrays; no allocs allowed) ----
__device__ float g_G1re[NIMG*H_*KX];   // stage1 output (img, y, kx)
__device__ float g_G1im[NIMG*H_*KX];
__device__ float g_mag [NIMG*H_*KX];   // log1p(|spec|)  (img, ky, kx)
__device__ float g_magup[NIMG*H_*W_];  // upsampled      (img, y, x)
__device__ ull   g_twp  [224];         // (cos, sin)
__device__ ull   g_twcc [224];         // (cos, cos)
__device__ ull   g_twss [224];         // (sin, sin)
__device__ ull   g_twnss[224];         // (-sin, -sin)
__device__ int   g_spk[T_*B_*CH_];     // spike counts per (t,b,ch)
__device__ float g_epart[1024];        // per-block mag partial sums

// ---------------------------------------------------------------------------
__global__ void k_init() {
    int tid = blockIdx.x*blockDim.x + threadIdx.x;
    if (tid < 224) {
        double a = (2.0*M_PI*(double)tid)/224.0;
        float c = (float)cos(a), s = (float)sin(a);
        g_twp  [tid] = pack2(c, s);
        g_twcc [tid] = pack2(c, c);
        g_twss [tid] = pack2(s, s);
        g_twnss[tid] = pack2(-s, -s);
    }
    for (int i = tid; i < T_*B_*CH_; i += gridDim.x*blockDim.x) g_spk[i] = 0;
}

// ---------------------------------------------------------------------------
// Stage 1: per image, per row y: X[k] = sum_x gray[x] * exp(-2pi i k x / 224)
// block = (ytile of 8, img). 256 threads: thread = (kgroup g in [0,32), yl in [0,8))
// each thread computes kx = g, g+32, g+64, g+96 for its row.
// Accumulator pair (re, +im), twiddle pair (cos, sin); im negated at store.
__global__ void __launch_bounds__(256) k_stage1(const float* __restrict__ x) {
    __shared__ float gray[8][225];         // padded rows
    __shared__ ull   twp[224];
    int img = blockIdx.y;
    int y0  = blockIdx.x * 8;
    int tid = threadIdx.x;
    for (int i = tid; i < 224; i += 256) twp[i] = g_twp[i];
    const float* xb = x + (size_t)img * H_ * W_ * C_;
    for (int i = tid; i < 8*224; i += 256) {
        int yl = i / 224, xx = i % 224;
        const float* p = xb + ((size_t)(y0+yl)*224 + xx)*3;
        gray[yl][xx] = (p[0] + p[1] + p[2]) * (1.0f/3.0f);
    }
    __syncthreads();

    int g = tid >> 3, yl = tid & 7;
    ull P0 = 0, P1 = 0, P2 = 0, P3 = 0;     // packed (re, im)
    int m0 = 0, m1 = 0, m2 = 0, m3 = 0;
    int k0 = g, k1 = g+32, k2 = g+64, k3 = g+96;
    #pragma unroll 4
    for (int xx = 0; xx < 224; xx++) {
        float gv = gray[yl][xx];
        ull gp = pack2(gv, gv);
        P0 = fma2(gp, twp[m0], P0);  m0 += k0; if (m0 >= 224) m0 -= 224;
        P1 = fma2(gp, twp[m1], P1);  m1 += k1; if (m1 >= 224) m1 -= 224;
        P2 = fma2(gp, twp[m2], P2);  m2 += k2; if (m2 >= 224) m2 -= 224;
        P3 = fma2(gp, twp[m3], P3);  m3 += k3; if (m3 >= 224) m3 -= 224;
    }
    float* outre = g_G1re + (size_t)img*H_*KX + (size_t)(y0+yl)*KX;
    float* outim = g_G1im + (size_t)img*H_*KX + (size_t)(y0+yl)*KX;
    float re, im;
    unpack2(P0, re, im); if (k0 < KX) { outre[k0] = re; outim[k0] = -im; }
    unpack2(P1, re, im); if (k1 < KX) { outre[k1] = re; outim[k1] = -im; }
    unpack2(P2, re, im); if (k2 < KX) { outre[k2] = re; outim[k2] = -im; }
    unpack2(P3, re, im); if (k3 < KX) { outre[k3] = re; outim[k3] = -im; }
}

// ---------------------------------------------------------------------------
// Stage 2: spec[ky,kx] = sum_y G1[y,kx] * exp(-2pi i ky y / 224), then
// mag = log1p(|spec|) + per-block partial sums for the energy output.
// block = (kx tile of 16, img). 256 threads: thread = (kxg in [0,8) -> kx pair,
// kyg in [0,32) -> 7 ky). Accumulators packed across the kx pair.
__global__ void __launch_bounds__(256) k_stage2() {
    __shared__ ull   sReP[224][8];        // packed (kx even, kx odd)
    __shared__ ull   sImP[224][8];
    __shared__ ull   twcc[224], twss[224], twnss[224];
    __shared__ float red[256];
    int img = blockIdx.y;
    int kxb = blockIdx.x * 16;
    int tid = threadIdx.x;
    for (int i = tid; i < 224; i += 256) {
        twcc[i] = g_twcc[i]; twss[i] = g_twss[i]; twnss[i] = g_twnss[i];
    }
    const float* inre = g_G1re + (size_t)img*H_*KX;
    const float* inim = g_G1im + (size_t)img*H_*KX;
    for (int i = tid; i < 224*8; i += 256) {
        int y = i >> 3, kp = i & 7;
        int kxA = kxb + kp*2, kxB = kxA + 1;
        float ra = (kxA < KX) ? inre[y*KX + kxA] : 0.f;
        float rb = (kxB < KX) ? inre[y*KX + kxB] : 0.f;
        float ia = (kxA < KX) ? inim[y*KX + kxA] : 0.f;
        float ib = (kxB < KX) ? inim[y*KX + kxB] : 0.f;
        sReP[y][kp] = pack2(ra, rb);
        sImP[y][kp] = pack2(ia, ib);
    }
    __syncthreads();

    int kxg = tid & 7;  int kyg = tid >> 3;
    ull RR[7], RI[7];
    int m[7];
    #pragma unroll
    for (int j = 0; j < 7; j++) { RR[j] = 0; RI[j] = 0; m[j] = 0; }

    for (int y = 0; y < 224; y++) {
        ull aP = sReP[y][kxg];
        ull bP = sImP[y][kxg];
        #pragma unroll
        for (int j = 0; j < 7; j++) {
            ull cc = twcc[m[j]], ss = twss[m[j]], ns = twnss[m[j]];
            RR[j] = fma2(aP, cc, RR[j]);
            RR[j] = fma2(bP, ss, RR[j]);
            RI[j] = fma2(bP, cc, RI[j]);
            RI[j] = fma2(aP, ns, RI[j]);
            m[j] += kyg + 32*j; if (m[j] >= 224) m[j] -= 224;
        }
    }

    float esum = 0.f;
    float* outm = g_mag + (size_t)img*H_*KX;
    #pragma unroll
    for (int j = 0; j < 7; j++) {
        int ky = kyg + 32*j;
        int kxA = kxb + kxg*2, kxB = kxA + 1;
        float rr0, rr1, ri0, ri1;
        unpack2(RR[j], rr0, rr1);
        unpack2(RI[j], ri0, ri1);
        if (kxA < KX) {
            float v = log1pf(sqrtf(fmaf(rr0, rr0, ri0*ri0)));
            outm[ky*KX + kxA] = v; esum += v;
        }
        if (kxB < KX) {
            float v = log1pf(sqrtf(fmaf(rr1, rr1, ri1*ri1)));
            outm[ky*KX + kxB] = v; esum += v;
        }
    }
    red[tid] = esum; __syncthreads();
    for (int s = 128; s > 0; s >>= 1) { if (tid < s) red[tid] += red[tid+s]; __syncthreads(); }
    if (tid == 0) g_epart[img*8 + blockIdx.x] = red[0];
}

// ---------------------------------------------------------------------------
// Upsample mag (img,y,113) -> (img,y,224): jax.image.resize 'linear'
// (half-pixel centers; boundary weight renormalization == clamp).
__global__ void k_upsample() {
    int idx = blockIdx.x*blockDim.x + threadIdx.x;
    if (idx >= NIMG*H_*W_) return;
    int j = idx % 224; int rest = idx / 224;       // rest = img*224 + y
    const float* row = g_mag + (size_t)rest * KX;
    float xsrc = (j + 0.5f) * (113.0f/224.0f) - 0.5f;
    float fi = floorf(xsrc);
    int i0 = (int)fi; float f = xsrc - fi;
    float v;
    if (i0 < 0)            v = row[0];
    else if (i0 >= KX - 1) v = row[KX-1];
    else { float a = row[i0]; v = fmaf(f, row[i0+1] - a, a); }
    g_magup[idx] = v;
}

// ---------------------------------------------------------------------------
// Fused conv3x3(4->32) + LIF over all 16 timesteps. V lives in registers as
// 16 packed f32x2 pairs. block = (16x16 spatial tile, batch b).
__global__ void __launch_bounds__(256) k_convlif(const float* __restrict__ x,
                                                 const float* __restrict__ convw,
                                                 const float* __restrict__ convb) {
    __shared__ ull   wshP[36*16];         // (p*4+ci, co-pair) packed pairs
    __shared__ ull   bshP[16];
    __shared__ float tile[4][18][19];     // [ci][y][x] padded halo tile
    __shared__ int   cnt[32];
    int tid = threadIdx.x;
    int b = blockIdx.y;
    int tileid = blockIdx.x;                 // 0..195
    int ty0 = (tileid / 14) * 16, tx0 = (tileid % 14) * 16;
    int ty = tid >> 4, tx = tid & 15;

    // convw last dim (co) contiguous -> adjacent float pairs == packed layout
    const ull* wsrc = (const ull*)convw;
    const ull* bsrc = (const ull*)convb;
    for (int i = tid; i < 576; i += 256) wshP[i] = wsrc[i];
    if (tid < 16) bshP[tid] = bsrc[tid];
    if (tid < 32) cnt[tid] = 0;

    const ull betaP = pack2(0.9f, 0.9f);
    ull V2[16];
    #pragma unroll
    for (int c = 0; c < 16; c++) V2[c] = 0;

    for (int t = 0; t < T_; t++) {
        int img = t*B_ + b;
        const float* xb = x + (size_t)img * H_ * W_ * C_;
        const float* mb = g_magup + (size_t)img * H_ * W_;
        // load halo tile (zero-padded SAME conv)
        for (int i = tid; i < 324; i += 256) {
            int yy = i / 18, xx = i % 18;
            int gy = ty0 + yy - 1, gx = tx0 + xx - 1;
            float v0=0.f, v1=0.f, v2=0.f, v3=0.f;
            if (gy >= 0 && gy < H_ && gx >= 0 && gx < W_) {
                const float* p = xb + ((size_t)gy*W_ + gx)*3;
                v0 = p[0]; v1 = p[1]; v2 = p[2];
                v3 = mb[gy*W_ + gx];
            }
            tile[0][yy][xx]=v0; tile[1][yy][xx]=v1; tile[2][yy][xx]=v2; tile[3][yy][xx]=v3;
        }
        __syncthreads();   // tile + (first iter) wshP/bshP/cnt ready

        // V = beta*V + bias
        #pragma unroll
        for (int c = 0; c < 16; c++) V2[c] = fma2(V2[c], betaP, bshP[c]);

        // conv accumulate
        #pragma unroll
        for (int p = 0; p < 9; p++) {
            int dy = p / 3, dx = p % 3;
            #pragma unroll
            for (int ci = 0; ci < 4; ci++) {
                float v = tile[ci][ty+dy][tx+dx];
                ull vv = pack2(v, v);
                const ull* wrow = &wshP[(p*4 + ci)*16];
                #pragma unroll
                for (int c = 0; c < 16; c++)
                    V2[c] = fma2(vv, wrow[c], V2[c]);
            }
        }
        // spike + soft reset
        unsigned mask = 0;
        #pragma unroll
        for (int c = 0; c < 16; c++) {
            float v0, v1;
            unpack2(V2[c], v0, v1);
            bool s0 = (v0 - 1.0f) > 0.f;
            bool s1 = (v1 - 1.0f) > 0.f;
            v0 -= s0 ? 1.0f : 0.0f;
            v1 -= s1 ? 1.0f : 0.0f;
            V2[c] = pack2(v0, v1);
            mask |= (s0 ? 1u : 0u) << (2*c);
            mask |= (s1 ? 1u : 0u) << (2*c+1);
        }
        // per-warp per-channel counts via ballot; channel ch -> lane ch
        int lane = tid & 31;
        int myc = 0;
        #pragma unroll
        for (int c = 0; c < 32; c++) {
            unsigned bal = __ballot_sync(0xffffffffu, (mask >> c) & 1u);
            if (lane == c) myc = __popc(bal);
        }
        atomicAdd(&cnt[lane], myc);
        __syncthreads();
        if (tid < 32) {
            atomicAdd(&g_spk[(t*B_ + b)*32 + tid], cnt[tid]);
            cnt[tid] = 0;
        }
        __syncthreads();   // keep next-iter tile load from racing cnt consumers
    }
}

// ---------------------------------------------------------------------------
__global__ void k_final(const float* __restrict__ head_w,
                        const float* __restrict__ head_b,
                        float* __restrict__ out) {
    __shared__ float red[256];
    int tid = threadIdx.x;
    // total spike count
    float acc = 0.f;
    for (int i = tid; i < T_*B_*CH_; i += 256) acc += (float)g_spk[i];
    red[tid] = acc; __syncthreads();
    for (int s = 128; s > 0; s >>= 1) { if (tid < s) red[tid] += red[tid+s]; __syncthreads(); }
    float totspk = red[0];
    __syncthreads();
    // energy
    float e = 0.f;
    for (int i = tid; i < 1024; i += 256) e += g_epart[i];
    red[tid] = e; __syncthreads();
    for (int s = 128; s > 0; s >>= 1) { if (tid < s) red[tid] += red[tid+s]; __syncthreads(); }
    float etot = red[0];

    // logits_seq at out[80 .. 80+1280)
    for (int idx = tid; idx < T_*B_*OUT_; idx += 256) {
        int o = idx % OUT_; int tb = idx / OUT_;
        const int* sp = &g_spk[tb*32];
        float s = 0.f;
        #pragma unroll
        for (int c = 0; c < 32; c++) s = fmaf((float)sp[c], head_w[c*OUT_ + o], s);
        out[80 + idx] = s * (1.0f/(float)(H_*W_)) + head_b[o];
    }
    __syncthreads();
    // readout = mean over t, at out[0..80)
    for (int idx = tid; idx < B_*OUT_; idx += 256) {
        int b = idx / OUT_, o = idx % OUT_;
        float s = 0.f;
        for (int t = 0; t < T_; t++) s += out[80 + ((t*B_ + b)*OUT_ + o)];
        out[idx] = s * (1.0f/(float)T_);
    }
    if (tid == 0) {
        out[80 + T_*B_*OUT_]     = totspk / ((float)T_*B_*H_*W_*CH_);
        out[80 + T_*B_*OUT_ + 1] = etot   / ((float)NIMG*H_*KX);
    }
}

// ---------------------------------------------------------------------------
extern "C" void kernel_launch(void* const* d_in, const int* in_sizes, int n_in,
                              void* d_out, int out_size) {
    const float* x     = (const float*)d_in[0];   // (16,8,224,224,3)
    const float* convw = (const float*)d_in[1];   // (3,3,4,32)
    const float* convb = (const float*)d_in[2];   // (32,)
    const float* headw = (const float*)d_in[3];   // (32,10)
    const float* headb = (const float*)d_in[4];   // (10,)
    float* out = (float*)d_out;

    k_init<<<16, 256>>>();
    { dim3 g(28, NIMG); k_stage1<<<g, 256>>>(x); }
    { dim3 g(8,  NIMG); k_stage2<<<g, 256>>>(); }
    k_upsample<<<(NIMG*H_*W_ + 255)/256, 256>>>();
    { dim3 g(196, B_); k_convlif<<<g, 256>>>(x, convw, convb); }
    k_final<<<1, 256>>>(headw, headb, out);
}

// round 3
// speedup vs baseline: 1.2025x; 1.2025x over previous
#include <cuda_runtime.h>
#include <math.h>

#define T_   16
#define B_   8
#define H_   224
#define W_   224
#define C_   3
#define CH_  32
#define OUT_ 10
#define NIMG (T_*B_)     // 128
#define KX   113         // W/2+1

typedef unsigned long long ull;

// ---- packed f32x2 helpers (FFMA2 path; ptxas won't auto-fuse) ----
__device__ __forceinline__ ull pack2(float lo, float hi) {
    ull r;
    asm("mov.b64 %0, {%1, %2};" : "=l"(r) : "f"(lo), "f"(hi));
    return r;
}
__device__ __forceinline__ void unpack2(ull v, float& lo, float& hi) {
    asm("mov.b64 {%0, %1}, %2;" : "=f"(lo), "=f"(hi) : "l"(v));
}
__device__ __forceinline__ ull fma2(ull a, ull b, ull c) {
    ull d;
    asm("fma.rn.f32x2 %0, %1, %2, %3;" : "=l"(d) : "l"(a), "l"(b), "l"(c));
    return d;
}

// ---- scratch (static device arrays; no allocs allowed) ----
__device__ float g_G1re[NIMG*H_*KX];   // stage1 output (img, y, kx)
__device__ float g_G1im[NIMG*H_*KX];
__device__ float g_mag [NIMG*H_*KX];   // log1p(|spec|)  (img, ky, kx)
__device__ float g_magup[NIMG*H_*W_];  // upsampled      (img, y, x)
__device__ ull   g_twp  [224];         // (cos, sin)
__device__ ull   g_twcc [224];         // (cos, cos)
__device__ ull   g_twss [224];         // (sin, sin)
__device__ ull   g_twnss[224];         // (-sin, -sin)
__device__ int   g_spk[T_*B_*CH_];     // spike counts per (t,b,ch)
__device__ float g_epart[1024];        // per-block mag partial sums

// ---------------------------------------------------------------------------
__global__ void k_init() {
    int tid = blockIdx.x*blockDim.x + threadIdx.x;
    if (tid < 224) {
        double a = (2.0*M_PI*(double)tid)/224.0;
        float c = (float)cos(a), s = (float)sin(a);
        g_twp  [tid] = pack2(c, s);
        g_twcc [tid] = pack2(c, c);
        g_twss [tid] = pack2(s, s);
        g_twnss[tid] = pack2(-s, -s);
    }
    for (int i = tid; i < T_*B_*CH_; i += gridDim.x*blockDim.x) g_spk[i] = 0;
    for (int i = tid; i < 1024; i += gridDim.x*blockDim.x) g_epart[i] = 0.f;
}

// ---------------------------------------------------------------------------
// Stage 1: row DFT. Block covers 32 rows of one image; thread = (kgroup g, ytile)
// computing 4 k values (g, g+32, g+64, g+96) x 4 rows. Twiddle load + index
// math amortized over the 4 rows.
__global__ void __launch_bounds__(256) k_stage1(const float* __restrict__ x) {
    __shared__ float gray[32][225];
    __shared__ ull   twp[224];
    int img = blockIdx.y;
    int y0  = blockIdx.x * 32;
    int tid = threadIdx.x;
    for (int i = tid; i < 224; i += 256) twp[i] = g_twp[i];
    const float* xb = x + (size_t)img * H_ * W_ * C_;
    for (int i = tid; i < 32*224; i += 256) {
        int yl = i / 224, xx = i % 224;
        const float* p = xb + ((size_t)(y0+yl)*224 + xx)*3;
        gray[yl][xx] = (p[0] + p[1] + p[2]) * (1.0f/3.0f);
    }
    __syncthreads();

    int g  = tid >> 3;          // 0..31  (k group)
    int yt = tid & 7;           // 0..7   (row group of 4)
    int r0 = yt * 4;
    int k0 = g, k1 = g+32, k2 = g+64, k3 = g+96;
    ull P[16];                  // P[j*4+r] = packed (re, +im) for k_j, row r
    #pragma unroll
    for (int i = 0; i < 16; i++) P[i] = 0;
    int m0 = 0, m1 = 0, m2 = 0, m3 = 0;

    #pragma unroll 2
    for (int xx = 0; xx < 224; xx++) {
        float ga = gray[r0  ][xx];
        float gb = gray[r0+1][xx];
        float gc = gray[r0+2][xx];
        float gd = gray[r0+3][xx];
        ull gpa = pack2(ga, ga), gpb = pack2(gb, gb);
        ull gpc = pack2(gc, gc), gpd = pack2(gd, gd);
        ull t;
        t = twp[m0];
        P[0]  = fma2(gpa, t, P[0]);  P[1]  = fma2(gpb, t, P[1]);
        P[2]  = fma2(gpc, t, P[2]);  P[3]  = fma2(gpd, t, P[3]);
        m0 += k0; if (m0 >= 224) m0 -= 224;
        t = twp[m1];
        P[4]  = fma2(gpa, t, P[4]);  P[5]  = fma2(gpb, t, P[5]);
        P[6]  = fma2(gpc, t, P[6]);  P[7]  = fma2(gpd, t, P[7]);
        m1 += k1; if (m1 >= 224) m1 -= 224;
        t = twp[m2];
        P[8]  = fma2(gpa, t, P[8]);  P[9]  = fma2(gpb, t, P[9]);
        P[10] = fma2(gpc, t, P[10]); P[11] = fma2(gpd, t, P[11]);
        m2 += k2; if (m2 >= 224) m2 -= 224;
        t = twp[m3];
        P[12] = fma2(gpa, t, P[12]); P[13] = fma2(gpb, t, P[13]);
        P[14] = fma2(gpc, t, P[14]); P[15] = fma2(gpd, t, P[15]);
        m3 += k3; if (m3 >= 224) m3 -= 224;
    }

    #pragma unroll
    for (int j = 0; j < 4; j++) {
        int k = g + 32*j;
        if (k < KX) {
            #pragma unroll
            for (int r = 0; r < 4; r++) {
                float re, im;
                unpack2(P[j*4 + r], re, im);
                size_t idx = (size_t)img*H_*KX + (size_t)(y0 + r0 + r)*KX + k;
                g_G1re[idx] = re;
                g_G1im[idx] = -im;
            }
        }
    }
}

// ---------------------------------------------------------------------------
// Stage 2: column DFT + log-magnitude + energy partials.
// Block covers 32 kx (16 packed pairs) of one image, all 224 ky.
// Thread = (kxg in [0,8) -> pairs kxg and kxg+8, kyg in [0,32) -> 7 ky).
// y is staged through smem in two 112-row chunks.
__global__ void __launch_bounds__(256) k_stage2() {
    __shared__ ull   sReP[112][16];
    __shared__ ull   sImP[112][16];
    __shared__ ull   twcc[224], twss[224], twnss[224];
    __shared__ float red[256];
    int img = blockIdx.y;
    int kxb = blockIdx.x * 32;      // 32 kx per block, grid.x = 4
    int tid = threadIdx.x;
    for (int i = tid; i < 224; i += 256) {
        twcc[i] = g_twcc[i]; twss[i] = g_twss[i]; twnss[i] = g_twnss[i];
    }
    const float* inre = g_G1re + (size_t)img*H_*KX;
    const float* inim = g_G1im + (size_t)img*H_*KX;

    int kxg = tid & 7;              // pairs kxg, kxg+8
    int kyg = tid >> 3;             // ky = kyg + 32*j
    ull RR0[7], RI0[7], RR1[7], RI1[7];
    int m[7];
    #pragma unroll
    for (int j = 0; j < 7; j++) { RR0[j]=RI0[j]=RR1[j]=RI1[j]=0; m[j]=0; }

    for (int chunk = 0; chunk < 2; chunk++) {
        __syncthreads();
        int ybase = chunk * 112;
        for (int i = tid; i < 112*16; i += 256) {
            int yy = i >> 4, kp = i & 15;
            int y = ybase + yy;
            int kxA = kxb + kp*2, kxB = kxA + 1;
            float ra = (kxA < KX) ? inre[y*KX + kxA] : 0.f;
            float rb = (kxB < KX) ? inre[y*KX + kxB] : 0.f;
            float ia = (kxA < KX) ? inim[y*KX + kxA] : 0.f;
            float ib = (kxB < KX) ? inim[y*KX + kxB] : 0.f;
            sReP[yy][kp] = pack2(ra, rb);
            sImP[yy][kp] = pack2(ia, ib);
        }
        __syncthreads();
        for (int yy = 0; yy < 112; yy++) {
            ull aP0 = sReP[yy][kxg],   bP0 = sImP[yy][kxg];
            ull aP1 = sReP[yy][kxg+8], bP1 = sImP[yy][kxg+8];
            #pragma unroll
            for (int j = 0; j < 7; j++) {
                ull cc = twcc[m[j]], ss = twss[m[j]], ns = twnss[m[j]];
                RR0[j] = fma2(aP0, cc, RR0[j]);
                RR0[j] = fma2(bP0, ss, RR0[j]);
                RI0[j] = fma2(bP0, cc, RI0[j]);
                RI0[j] = fma2(aP0, ns, RI0[j]);
                RR1[j] = fma2(aP1, cc, RR1[j]);
                RR1[j] = fma2(bP1, ss, RR1[j]);
                RI1[j] = fma2(bP1, cc, RI1[j]);
                RI1[j] = fma2(aP1, ns, RI1[j]);
                m[j] += kyg + 32*j; if (m[j] >= 224) m[j] -= 224;
            }
        }
    }

    float esum = 0.f;
    float* outm = g_mag + (size_t)img*H_*KX;
    #pragma unroll
    for (int j = 0; j < 7; j++) {
        int ky = kyg + 32*j;
        int kxA = kxb + kxg*2;
        int kxC = kxb + (kxg+8)*2;
        float a0,a1,b0,b1;
        unpack2(RR0[j], a0, a1); unpack2(RI0[j], b0, b1);
        if (kxA < KX) {
            float v = log1pf(sqrtf(fmaf(a0, a0, b0*b0)));
            outm[ky*KX + kxA] = v; esum += v;
        }
        if (kxA+1 < KX) {
            float v = log1pf(sqrtf(fmaf(a1, a1, b1*b1)));
            outm[ky*KX + kxA+1] = v; esum += v;
        }
        unpack2(RR1[j], a0, a1); unpack2(RI1[j], b0, b1);
        if (kxC < KX) {
            float v = log1pf(sqrtf(fmaf(a0, a0, b0*b0)));
            outm[ky*KX + kxC] = v; esum += v;
        }
        if (kxC+1 < KX) {
            float v = log1pf(sqrtf(fmaf(a1, a1, b1*b1)));
            outm[ky*KX + kxC+1] = v; esum += v;
        }
    }
    red[tid] = esum; __syncthreads();
    for (int s = 128; s > 0; s >>= 1) { if (tid < s) red[tid] += red[tid+s]; __syncthreads(); }
    if (tid == 0) g_epart[img*4 + blockIdx.x] = red[0];
}

// ---------------------------------------------------------------------------
// Upsample mag (img,y,113) -> (img,y,224): jax.image.resize 'linear'
// (half-pixel centers; boundary weight renormalization == clamp).
__global__ void k_upsample() {
    int idx = blockIdx.x*blockDim.x + threadIdx.x;
    if (idx >= NIMG*H_*W_) return;
    int j = idx % 224; int rest = idx / 224;       // rest = img*224 + y
    const float* row = g_mag + (size_t)rest * KX;
    float xsrc = (j + 0.5f) * (113.0f/224.0f) - 0.5f;
    float fi = floorf(xsrc);
    int i0 = (int)fi; float f = xsrc - fi;
    float v;
    if (i0 < 0)            v = row[0];
    else if (i0 >= KX - 1) v = row[KX-1];
    else { float a = row[i0]; v = fmaf(f, row[i0+1] - a, a); }
    g_magup[idx] = v;
}

// ---------------------------------------------------------------------------
// Fused conv3x3(4->32) + LIF over all 16 timesteps. Each thread owns TWO
// vertically-adjacent pixels x 32 channels (V in 32 packed f32x2 regs);
// weight LDS amortized over both pixels. Tile = 16 wide x 32 high.
__global__ void __launch_bounds__(256) k_convlif(const float* __restrict__ x,
                                                 const float* __restrict__ convw,
                                                 const float* __restrict__ convb) {
    __shared__ ull   wshP[36*16];         // (p*4+ci, co-pair)
    __shared__ ull   bshP[16];
    __shared__ float tile[4][34][19];     // [ci][y][x] halo tile (32h+2, 16w+2, pad)
    __shared__ int   cnt[32];
    int tid = threadIdx.x;
    int b = blockIdx.y;
    int tileid = blockIdx.x;                 // 0..97
    int ty0 = (tileid / 14) * 32, tx0 = (tileid % 14) * 16;
    int ty2 = tid >> 4;                      // 0..15 -> rows 2*ty2, 2*ty2+1
    int tx  = tid & 15;

    const ull* wsrc = (const ull*)convw;
    const ull* bsrc = (const ull*)convb;
    for (int i = tid; i < 576; i += 256) wshP[i] = wsrc[i];
    if (tid < 16) bshP[tid] = bsrc[tid];
    if (tid < 32) cnt[tid] = 0;

    const ull betaP = pack2(0.9f, 0.9f);
    ull VA[16], VB[16];
    #pragma unroll
    for (int c = 0; c < 16; c++) { VA[c] = 0; VB[c] = 0; }

    for (int t = 0; t < T_; t++) {
        int img = t*B_ + b;
        const float* xb = x + (size_t)img * H_ * W_ * C_;
        const float* mb = g_magup + (size_t)img * H_ * W_;
        // load halo tile (zero-padded SAME conv): 34 x 18
        for (int i = tid; i < 34*18; i += 256) {
            int yy = i / 18, xx = i % 18;
            int gy = ty0 + yy - 1, gx = tx0 + xx - 1;
            float v0=0.f, v1=0.f, v2=0.f, v3=0.f;
            if (gy >= 0 && gy < H_ && gx >= 0 && gx < W_) {
                const float* p = xb + ((size_t)gy*W_ + gx)*3;
                v0 = p[0]; v1 = p[1]; v2 = p[2];
                v3 = mb[gy*W_ + gx];
            }
            tile[0][yy][xx]=v0; tile[1][yy][xx]=v1; tile[2][yy][xx]=v2; tile[3][yy][xx]=v3;
        }
        __syncthreads();   // tile (+ first-iter wshP/bshP/cnt) ready

        #pragma unroll
        for (int c = 0; c < 16; c++) {
            VA[c] = fma2(VA[c], betaP, bshP[c]);
            VB[c] = fma2(VB[c], betaP, bshP[c]);
        }

        #pragma unroll
        for (int p = 0; p < 9; p++) {
            int dy = p / 3, dx = p % 3;
            #pragma unroll
            for (int ci = 0; ci < 4; ci++) {
                float v0 = tile[ci][2*ty2   + dy][tx + dx];
                float v1 = tile[ci][2*ty2+1 + dy][tx + dx];
                ull vv0 = pack2(v0, v0);
                ull vv1 = pack2(v1, v1);
                const ull* wrow = &wshP[(p*4 + ci)*16];
                #pragma unroll
                for (int c = 0; c < 16; c++) {
                    ull w = wrow[c];
                    VA[c] = fma2(vv0, w, VA[c]);
                    VB[c] = fma2(vv1, w, VB[c]);
                }
            }
        }
        // spike + soft reset, both pixels
        unsigned mask0 = 0, mask1 = 0;
        #pragma unroll
        for (int c = 0; c < 16; c++) {
            float a0, a1, b0v, b1v;
            unpack2(VA[c], a0, a1);
            unpack2(VB[c], b0v, b1v);
            bool sa0 = (a0 - 1.0f) > 0.f;  bool sa1 = (a1 - 1.0f) > 0.f;
            bool sb0 = (b0v - 1.0f) > 0.f; bool sb1 = (b1v - 1.0f) > 0.f;
            a0  -= sa0 ? 1.0f : 0.0f;  a1  -= sa1 ? 1.0f : 0.0f;
            b0v -= sb0 ? 1.0f : 0.0f;  b1v -= sb1 ? 1.0f : 0.0f;
            VA[c] = pack2(a0, a1);
            VB[c] = pack2(b0v, b1v);
            mask0 |= (sa0 ? 1u : 0u) << (2*c);
            mask0 |= (sa1 ? 1u : 0u) << (2*c+1);
            mask1 |= (sb0 ? 1u : 0u) << (2*c);
            mask1 |= (sb1 ? 1u : 0u) << (2*c+1);
        }
        int lane = tid & 31;
        int myc = 0;
        #pragma unroll
        for (int c = 0; c < 32; c++) {
            unsigned balA = __ballot_sync(0xffffffffu, (mask0 >> c) & 1u);
            unsigned balB = __ballot_sync(0xffffffffu, (mask1 >> c) & 1u);
            if (lane == c) myc = __popc(balA) + __popc(balB);
        }
        atomicAdd(&cnt[lane], myc);
        __syncthreads();
        if (tid < 32) {
            atomicAdd(&g_spk[(t*B_ + b)*32 + tid], cnt[tid]);
            cnt[tid] = 0;
        }
        __syncthreads();   // keep next-iter tile load from racing cnt consumers
    }
}

// ---------------------------------------------------------------------------
__global__ void k_final(const float* __restrict__ head_w,
                        const float* __restrict__ head_b,
                        float* __restrict__ out) {
    __shared__ float red[256];
    int tid = threadIdx.x;
    // total spike count
    float acc = 0.f;
    for (int i = tid; i < T_*B_*CH_; i += 256) acc += (float)g_spk[i];
    red[tid] = acc; __syncthreads();
    for (int s = 128; s > 0; s >>= 1) { if (tid < s) red[tid] += red[tid+s]; __syncthreads(); }
    float totspk = red[0];
    __syncthreads();
    // energy
    float e = 0.f;
    for (int i = tid; i < 1024; i += 256) e += g_epart[i];
    red[tid] = e; __syncthreads();
    for (int s = 128; s > 0; s >>= 1) { if (tid < s) red[tid] += red[tid+s]; __syncthreads(); }
    float etot = red[0];

    // logits_seq at out[80 .. 80+1280)
    for (int idx = tid; idx < T_*B_*OUT_; idx += 256) {
        int o = idx % OUT_; int tb = idx / OUT_;
        const int* sp = &g_spk[tb*32];
        float s = 0.f;
        #pragma unroll
        for (int c = 0; c < 32; c++) s = fmaf((float)sp[c], head_w[c*OUT_ + o], s);
        out[80 + idx] = s * (1.0f/(float)(H_*W_)) + head_b[o];
    }
    __syncthreads();
    // readout = mean over t, at out[0..80)
    for (int idx = tid; idx < B_*OUT_; idx += 256) {
        int b = idx / OUT_, o = idx % OUT_;
        float s = 0.f;
        for (int t = 0; t < T_; t++) s += out[80 + ((t*B_ + b)*OUT_ + o)];
        out[idx] = s * (1.0f/(float)T_);
    }
    if (tid == 0) {
        out[80 + T_*B_*OUT_]     = totspk / ((float)T_*B_*H_*W_*CH_);
        out[80 + T_*B_*OUT_ + 1] = etot   / ((float)NIMG*H_*KX);
    }
}

// ---------------------------------------------------------------------------
extern "C" void kernel_launch(void* const* d_in, const int* in_sizes, int n_in,
                              void* d_out, int out_size) {
    const float* x     = (const float*)d_in[0];   // (16,8,224,224,3)
    const float* convw = (const float*)d_in[1];   // (3,3,4,32)
    const float* convb = (const float*)d_in[2];   // (32,)
    const float* headw = (const float*)d_in[3];   // (32,10)
    const float* headb = (const float*)d_in[4];   // (10,)
    float* out = (float*)d_out;

    k_init<<<16, 256>>>();
    { dim3 g(7,  NIMG); k_stage1<<<g, 256>>>(x); }
    { dim3 g(4,  NIMG); k_stage2<<<g, 256>>>(); }
    k_upsample<<<(NIMG*H_*W_ + 255)/256, 256>>>();
    { dim3 g(98, B_); k_convlif<<<g, 256>>>(x, convw, convb); }
    k_final<<<1, 256>>>(headw, headb, out);
}

// round 4
// speedup vs baseline: 1.3742x; 1.1429x over previous
#include <cuda_runtime.h>
#include <math.h>

#define T_   16
#define B_   8
#define H_   224
#define W_   224
#define C_   3
#define CH_  32
#define OUT_ 10
#define NIMG (T_*B_)     // 128
#define KX   113         // W/2+1

typedef unsigned long long ull;

// ---- packed f32x2 helpers ----
__device__ __forceinline__ ull pack2(float lo, float hi) {
    ull r;
    asm("mov.b64 %0, {%1, %2};" : "=l"(r) : "f"(lo), "f"(hi));
    return r;
}
__device__ __forceinline__ void unpack2(ull v, float& lo, float& hi) {
    asm("mov.b64 {%0, %1}, %2;" : "=f"(lo), "=f"(hi) : "l"(v));
}
__device__ __forceinline__ ull fma2(ull a, ull b, ull c) {
    ull d;
    asm("fma.rn.f32x2 %0, %1, %2, %3;" : "=l"(d) : "l"(a), "l"(b), "l"(c));
    return d;
}

// ---- scratch ----
__device__ float g_G1re[NIMG*H_*KX];   // stage1 output (img, y, kx)
__device__ float g_G1im[NIMG*H_*KX];
__device__ float g_mag [NIMG*H_*KX];   // log1p(|spec|)  (img, ky, kx)
__device__ ull   g_twp  [224];         // (cos, sin)
__device__ ull   g_twcc [224];         // (cos, cos)
__device__ ull   g_twss [224];         // (sin, sin)
__device__ int   g_spk[T_*B_*CH_];     // spike counts per (t,b,ch)
__device__ float g_epart[1024];        // per-block mag partial sums

// ---------------------------------------------------------------------------
__global__ void k_init() {
    int tid = blockIdx.x*blockDim.x + threadIdx.x;
    if (tid < 224) {
        double a = (2.0*M_PI*(double)tid)/224.0;
        float c = (float)cos(a), s = (float)sin(a);
        g_twp [tid] = pack2(c, s);
        g_twcc[tid] = pack2(c, c);
        g_twss[tid] = pack2(s, s);
    }
    for (int i = tid; i < T_*B_*CH_; i += gridDim.x*blockDim.x) g_spk[i] = 0;
    for (int i = tid; i < 1024; i += gridDim.x*blockDim.x) g_epart[i] = 0.f;
}

// ---------------------------------------------------------------------------
// Stage 1: row DFT with real-input x-fold.
// X[k] = g0 + (-1)^k g112 + sum_{x=1..111} [ S(x)cos - i D(x)sin ],
// S = g[x]+g[224-x], D = g[x]-g[224-x].
// One fma2 per (x-pair, k): acc = (Sum S cos, Sum D sin); Im = -acc.hi.
// Block: 32 rows of one image. Thread = (kgroup g in [0,32), ytile in [0,8)):
// 4 k-values (g+32j) x 4 rows.
__global__ void __launch_bounds__(256) k_stage1(const float* __restrict__ x) {
    __shared__ ull   sd[32][111];        // pack2(S, D), x-1 indexed
    __shared__ ull   twp[224];
    __shared__ float ge0[32], ge1[32];   // g[0], g[112] per row
    int img = blockIdx.y;
    int y0  = blockIdx.x * 32;
    int tid = threadIdx.x;
    for (int i = tid; i < 224; i += 256) twp[i] = g_twp[i];
    const float* xb = x + (size_t)img * H_ * W_ * C_;
    for (int i = tid; i < 32*112; i += 256) {
        int yl = i / 112, xx = i % 112;
        int gy = y0 + yl;
        const float* rowp = xb + (size_t)gy * W_ * 3;
        if (xx == 0) {
            ge0[yl] = (rowp[0]     + rowp[1]     + rowp[2]    ) * (1.0f/3.0f);
            const float* q = rowp + 112*3;
            ge1[yl] = (q[0] + q[1] + q[2]) * (1.0f/3.0f);
        } else {
            const float* pa = rowp + xx*3;
            const float* pb = rowp + (224 - xx)*3;
            float a = (pa[0] + pa[1] + pa[2]) * (1.0f/3.0f);
            float b = (pb[0] + pb[1] + pb[2]) * (1.0f/3.0f);
            sd[yl][xx-1] = pack2(a + b, a - b);
        }
    }
    __syncthreads();

    int g  = tid >> 3;          // 0..31
    int yt = tid & 7;           // 0..7
    int r0 = yt * 4;
    int k0 = g, k1 = g+32, k2 = g+64, k3 = g+96;
    ull P[16];
    #pragma unroll
    for (int i = 0; i < 16; i++) P[i] = 0;
    int m0 = k0, m1 = k1, m2 = k2, m3 = k3;   // m = k*x mod 224, x starts at 1

    #pragma unroll 2
    for (int xi = 0; xi < 111; xi++) {
        ull s0 = sd[r0  ][xi];
        ull s1 = sd[r0+1][xi];
        ull s2 = sd[r0+2][xi];
        ull s3 = sd[r0+3][xi];
        ull t;
        t = twp[m0];
        P[0]  = fma2(s0, t, P[0]);  P[1]  = fma2(s1, t, P[1]);
        P[2]  = fma2(s2, t, P[2]);  P[3]  = fma2(s3, t, P[3]);
        m0 += k0; if (m0 >= 224) m0 -= 224;
        t = twp[m1];
        P[4]  = fma2(s0, t, P[4]);  P[5]  = fma2(s1, t, P[5]);
        P[6]  = fma2(s2, t, P[6]);  P[7]  = fma2(s3, t, P[7]);
        m1 += k1; if (m1 >= 224) m1 -= 224;
        t = twp[m2];
        P[8]  = fma2(s0, t, P[8]);  P[9]  = fma2(s1, t, P[9]);
        P[10] = fma2(s2, t, P[10]); P[11] = fma2(s3, t, P[11]);
        m2 += k2; if (m2 >= 224) m2 -= 224;
        t = twp[m3];
        P[12] = fma2(s0, t, P[12]); P[13] = fma2(s1, t, P[13]);
        P[14] = fma2(s2, t, P[14]); P[15] = fma2(s3, t, P[15]);
        m3 += k3; if (m3 >= 224) m3 -= 224;
    }

    float par = (g & 1) ? -1.0f : 1.0f;   // (-1)^k, k = g+32j has parity of g
    #pragma unroll
    for (int j = 0; j < 4; j++) {
        int k = g + 32*j;
        if (k < KX) {
            #pragma unroll
            for (int r = 0; r < 4; r++) {
                float sc, ds;
                unpack2(P[j*4 + r], sc, ds);
                int row = r0 + r;
                size_t idx = (size_t)img*H_*KX + (size_t)(y0 + row)*KX + k;
                g_G1re[idx] = sc + ge0[row] + par*ge1[row];
                g_G1im[idx] = -ds;
            }
        }
    }
}

// ---------------------------------------------------------------------------
// Stage 2: column DFT with double fold (y and ky) + log-magnitude + energy.
// S(y)=G[y]+G[224-y], D(y)=G[y]-G[224-y] (complex), y=1..111.
// P1=Sum Sre*cos, P2=Sum Dim*sin, P3=Sum Sim*cos, P4=Sum Dre*sin (theta=2pi*ky*y/224)
// X[ky]     = (P1+P2) + i(P3-P4) + E ;  X[224-ky] = (P1-P2) + i(P3+P4) + E
// E = G[0] + (-1)^ky G[112].   X[0] = G[0]+G[112]+Sum S.
// Block: 32 kx (16 f32x2 lanes) of one image. Thread = (kyg=tid&15, kxp=tid>>4),
// 7 ky-pairs per thread (ky = 1+kyg+16j, j<7 -> ky 1..112). y staged in 2 chunks.
__global__ void __launch_bounds__(256) k_stage2() {
    __shared__ ull sSre[56][16], sSim[56][16], sDre[56][16], sDim[56][16];
    __shared__ ull tcc[224], tss[224];
    __shared__ float red[256];
    int img = blockIdx.y;
    int kxb = blockIdx.x * 32;
    int tid = threadIdx.x;
    int kyg = tid & 15;
    int kxp = tid >> 4;
    for (int i = tid; i < 224; i += 256) { tcc[i] = g_twcc[i]; tss[i] = g_twss[i]; }

    const float* inre = g_G1re + (size_t)img*H_*KX;
    const float* inim = g_G1im + (size_t)img*H_*KX;

    ull P1[7], P2[7], P3[7], P4[7];
    int m[7], kyv[7];
    #pragma unroll
    for (int j = 0; j < 7; j++) {
        P1[j]=P2[j]=P3[j]=P4[j]=0;
        kyv[j] = 1 + kyg + 16*j;
        m[j] = kyv[j];              // ky*y mod 224, y starts at 1
    }
    ull A0re = 0, A0im = 0;         // Sum S over y (for ky=0), kyg==0 lanes
    const ull ONE2 = pack2(1.0f, 1.0f);

    for (int chunk = 0; chunk < 2; chunk++) {
        int yb   = 1 + 56*chunk;
        int ycnt = chunk ? 55 : 56;
        __syncthreads();
        for (int i = tid; i < ycnt*16; i += 256) {
            int yy = i >> 4, kp = i & 15;
            int y = yb + yy;
            int kxA = kxb + 2*kp, kxB = kxA + 1;
            float reA  = (kxA < KX) ? inre[y*KX + kxA] : 0.f;
            float reB  = (kxB < KX) ? inre[y*KX + kxB] : 0.f;
            float imA  = (kxA < KX) ? inim[y*KX + kxA] : 0.f;
            float imB  = (kxB < KX) ? inim[y*KX + kxB] : 0.f;
            int ym = 224 - y;
            float reA2 = (kxA < KX) ? inre[ym*KX + kxA] : 0.f;
            float reB2 = (kxB < KX) ? inre[ym*KX + kxB] : 0.f;
            float imA2 = (kxA < KX) ? inim[ym*KX + kxA] : 0.f;
            float imB2 = (kxB < KX) ? inim[ym*KX + kxB] : 0.f;
            sSre[yy][kp] = pack2(reA + reA2, reB + reB2);
            sDre[yy][kp] = pack2(reA - reA2, reB - reB2);
            sSim[yy][kp] = pack2(imA + imA2, imB + imB2);
            sDim[yy][kp] = pack2(imA - imA2, imB - imB2);
        }
        __syncthreads();
        for (int yy = 0; yy < ycnt; yy++) {
            ull sre = sSre[yy][kxp], sim = sSim[yy][kxp];
            ull dre = sDre[yy][kxp], dim = sDim[yy][kxp];
            if (kyg == 0) {
                A0re = fma2(sre, ONE2, A0re);
                A0im = fma2(sim, ONE2, A0im);
            }
            #pragma unroll
            for (int j = 0; j < 7; j++) {
                ull cc = tcc[m[j]], ss = tss[m[j]];
                P1[j] = fma2(sre, cc, P1[j]);
                P2[j] = fma2(dim, ss, P2[j]);
                P3[j] = fma2(sim, cc, P3[j]);
                P4[j] = fma2(dre, ss, P4[j]);
                m[j] += kyv[j]; if (m[j] >= 224) m[j] -= 224;
            }
        }
    }

    // edge rows y=0, y=112
    int kxA = kxb + 2*kxp, kxB = kxA + 1;
    float G0reA  = (kxA < KX) ? inre[kxA]          : 0.f;
    float G0reB  = (kxB < KX) ? inre[kxB]          : 0.f;
    float G0imA  = (kxA < KX) ? inim[kxA]          : 0.f;
    float G0imB  = (kxB < KX) ? inim[kxB]          : 0.f;
    float G1reA  = (kxA < KX) ? inre[112*KX + kxA] : 0.f;
    float G1reB  = (kxB < KX) ? inre[112*KX + kxB] : 0.f;
    float G1imA  = (kxA < KX) ? inim[112*KX + kxA] : 0.f;
    float G1imB  = (kxB < KX) ? inim[112*KX + kxB] : 0.f;

    float esum = 0.f;
    float* outm = g_mag + (size_t)img*H_*KX;
    #pragma unroll
    for (int j = 0; j < 7; j++) {
        int ky = kyv[j];
        float par = (ky & 1) ? -1.0f : 1.0f;
        float p1A,p1B,p2A,p2B,p3A,p3B,p4A,p4B;
        unpack2(P1[j], p1A, p1B); unpack2(P2[j], p2A, p2B);
        unpack2(P3[j], p3A, p3B); unpack2(P4[j], p4A, p4B);
        float EreA = G0reA + par*G1reA, EreB = G0reB + par*G1reB;
        float EimA = G0imA + par*G1imA, EimB = G0imB + par*G1imB;
        if (kxA < KX) {
            float re = p1A + p2A + EreA, im = p3A - p4A + EimA;
            float v = log1pf(sqrtf(fmaf(re, re, im*im)));
            outm[ky*KX + kxA] = v; esum += v;
            if (ky != 112) {
                float re2 = p1A - p2A + EreA, im2 = p3A + p4A + EimA;
                float v2 = log1pf(sqrtf(fmaf(re2, re2, im2*im2)));
                outm[(224-ky)*KX + kxA] = v2; esum += v2;
            }
        }
        if (kxB < KX) {
            float re = p1B + p2B + EreB, im = p3B - p4B + EimB;
            float v = log1pf(sqrtf(fmaf(re, re, im*im)));
            outm[ky*KX + kxB] = v; esum += v;
            if (ky != 112) {
                float re2 = p1B - p2B + EreB, im2 = p3B + p4B + EimB;
                float v2 = log1pf(sqrtf(fmaf(re2, re2, im2*im2)));
                outm[(224-ky)*KX + kxB] = v2; esum += v2;
            }
        }
    }
    if (kyg == 0) {   // ky = 0 row
        float aA, aB, iA, iB;
        unpack2(A0re, aA, aB); unpack2(A0im, iA, iB);
        if (kxA < KX) {
            float re = aA + G0reA + G1reA, im = iA + G0imA + G1imA;
            float v = log1pf(sqrtf(fmaf(re, re, im*im)));
            outm[kxA] = v; esum += v;
        }
        if (kxB < KX) {
            float re = aB + G0reB + G1reB, im = iB + G0imB + G1imB;
            float v = log1pf(sqrtf(fmaf(re, re, im*im)));
            outm[kxB] = v; esum += v;
        }
    }
    red[tid] = esum; __syncthreads();
    for (int s = 128; s > 0; s >>= 1) { if (tid < s) red[tid] += red[tid+s]; __syncthreads(); }
    if (tid == 0) g_epart[img*4 + blockIdx.x] = red[0];
}

// ---------------------------------------------------------------------------
// Fused conv3x3(4->32) + LIF over 16 timesteps, with the spectral-channel
// bilinear upsample fused into the tile loader. Double-buffered packed tile,
// one sync per timestep, direct global spike atomics.
__global__ void __launch_bounds__(256, 2) k_convlif(const float* __restrict__ x,
                                                    const float* __restrict__ convw,
                                                    const float* __restrict__ convb) {
    __shared__ ull wshP[36*16];
    __shared__ ull bshP[16];
    __shared__ ull tile[2][4][34][19];    // packed (v,v)
    int tid = threadIdx.x;
    int b = blockIdx.y;
    int tileid = blockIdx.x;               // 0..97
    int ty0 = (tileid / 14) * 32, tx0 = (tileid % 14) * 16;
    int ty2 = tid >> 4;                    // rows 2*ty2, 2*ty2+1
    int tx  = tid & 15;
    int lane = tid & 31;

    const ull* wsrc = (const ull*)convw;
    const ull* bsrc = (const ull*)convb;
    for (int i = tid; i < 576; i += 256) wshP[i] = wsrc[i];
    if (tid < 16) bshP[tid] = bsrc[tid];

    const ull betaP = pack2(0.9f, 0.9f);
    ull VA[16], VB[16];
    #pragma unroll
    for (int c = 0; c < 16; c++) { VA[c] = 0; VB[c] = 0; }

    // tile loader (upsample fused for channel 3)
    auto loadTile = [&](int buf, int img) {
        const float* xb = x + (size_t)img * H_ * W_ * C_;
        const float* magb = g_mag + (size_t)img * H_ * KX;
        for (int i = tid; i < 34*18; i += 256) {
            int yy = i / 18, xx = i % 18;
            int gy = ty0 + yy - 1, gx = tx0 + xx - 1;
            float v0=0.f, v1=0.f, v2=0.f, v3=0.f;
            if (gy >= 0 && gy < H_ && gx >= 0 && gx < W_) {
                const float* p = xb + ((size_t)gy*W_ + gx)*3;
                v0 = p[0]; v1 = p[1]; v2 = p[2];
                float xsrc = (gx + 0.5f) * (113.0f/224.0f) - 0.5f;
                float fi = floorf(xsrc);
                int i0 = (int)fi; float f = xsrc - fi;
                const float* mrow = magb + gy*KX;
                if (i0 < 0)            v3 = mrow[0];
                else if (i0 >= KX - 1) v3 = mrow[KX-1];
                else { float a = mrow[i0]; v3 = fmaf(f, mrow[i0+1] - a, a); }
            }
            tile[buf][0][yy][xx] = pack2(v0, v0);
            tile[buf][1][yy][xx] = pack2(v1, v1);
            tile[buf][2][yy][xx] = pack2(v2, v2);
            tile[buf][3][yy][xx] = pack2(v3, v3);
        }
    };

    loadTile(0, 0*B_ + b);
    int cur = 0;
    for (int t = 0; t < T_; t++) {
        __syncthreads();    // tile[cur] ready; prev compute on tile[1-cur] done
        if (t + 1 < T_) loadTile(1 - cur, (t+1)*B_ + b);

        #pragma unroll
        for (int c = 0; c < 16; c++) {
            VA[c] = fma2(VA[c], betaP, bshP[c]);
            VB[c] = fma2(VB[c], betaP, bshP[c]);
        }
        #pragma unroll
        for (int p = 0; p < 9; p++) {
            int dy = p / 3, dx = p % 3;
            #pragma unroll
            for (int ci = 0; ci < 4; ci++) {
                ull vv0 = tile[cur][ci][2*ty2   + dy][tx + dx];
                ull vv1 = tile[cur][ci][2*ty2+1 + dy][tx + dx];
                const ull* wrow = &wshP[(p*4 + ci)*16];
                #pragma unroll
                for (int c = 0; c < 16; c++) {
                    ull w = wrow[c];
                    VA[c] = fma2(vv0, w, VA[c]);
                    VB[c] = fma2(vv1, w, VB[c]);
                }
            }
        }
        // spike + soft reset
        unsigned mask0 = 0, mask1 = 0;
        #pragma unroll
        for (int c = 0; c < 16; c++) {
            float a0, a1, b0v, b1v;
            unpack2(VA[c], a0, a1);
            unpack2(VB[c], b0v, b1v);
            bool sa0 = (a0 - 1.0f) > 0.f;  bool sa1 = (a1 - 1.0f) > 0.f;
            bool sb0 = (b0v - 1.0f) > 0.f; bool sb1 = (b1v - 1.0f) > 0.f;
            a0  -= sa0 ? 1.0f : 0.0f;  a1  -= sa1 ? 1.0f : 0.0f;
            b0v -= sb0 ? 1.0f : 0.0f;  b1v -= sb1 ? 1.0f : 0.0f;
            VA[c] = pack2(a0, a1);
            VB[c] = pack2(b0v, b1v);
            mask0 |= (sa0 ? 1u : 0u) << (2*c);
            mask0 |= (sa1 ? 1u : 0u) << (2*c+1);
            mask1 |= (sb0 ? 1u : 0u) << (2*c);
            mask1 |= (sb1 ? 1u : 0u) << (2*c+1);
        }
        int myc = 0;
        #pragma unroll
        for (int c = 0; c < 32; c++) {
            unsigned balA = __ballot_sync(0xffffffffu, (mask0 >> c) & 1u);
            unsigned balB = __ballot_sync(0xffffffffu, (mask1 >> c) & 1u);
            if (lane == c) myc = __popc(balA) + __popc(balB);
        }
        atomicAdd(&g_spk[(t*B_ + b)*32 + lane], myc);
        cur ^= 1;
    }
}

// ---------------------------------------------------------------------------
__global__ void k_final(const float* __restrict__ head_w,
                        const float* __restrict__ head_b,
                        float* __restrict__ out) {
    __shared__ float red[256];
    int tid = threadIdx.x;
    float acc = 0.f;
    for (int i = tid; i < T_*B_*CH_; i += 256) acc += (float)g_spk[i];
    red[tid] = acc; __syncthreads();
    for (int s = 128; s > 0; s >>= 1) { if (tid < s) red[tid] += red[tid+s]; __syncthreads(); }
    float totspk = red[0];
    __syncthreads();
    float e = 0.f;
    for (int i = tid; i < 1024; i += 256) e += g_epart[i];
    red[tid] = e; __syncthreads();
    for (int s = 128; s > 0; s >>= 1) { if (tid < s) red[tid] += red[tid+s]; __syncthreads(); }
    float etot = red[0];

    for (int idx = tid; idx < T_*B_*OUT_; idx += 256) {
        int o = idx % OUT_; int tb = idx / OUT_;
        const int* sp = &g_spk[tb*32];
        float s = 0.f;
        #pragma unroll
        for (int c = 0; c < 32; c++) s = fmaf((float)sp[c], head_w[c*OUT_ + o], s);
        out[80 + idx] = s * (1.0f/(float)(H_*W_)) + head_b[o];
    }
    __syncthreads();
    for (int idx = tid; idx < B_*OUT_; idx += 256) {
        int b = idx / OUT_, o = idx % OUT_;
        float s = 0.f;
        for (int t = 0; t < T_; t++) s += out[80 + ((t*B_ + b)*OUT_ + o)];
        out[idx] = s * (1.0f/(float)T_);
    }
    if (tid == 0) {
        out[80 + T_*B_*OUT_]     = totspk / ((float)T_*B_*H_*W_*CH_);
        out[80 + T_*B_*OUT_ + 1] = etot   / ((float)NIMG*H_*KX);
    }
}

// ---------------------------------------------------------------------------
extern "C" void kernel_launch(void* const* d_in, const int* in_sizes, int n_in,
                              void* d_out, int out_size) {
    const float* x     = (const float*)d_in[0];   // (16,8,224,224,3)
    const float* convw = (const float*)d_in[1];   // (3,3,4,32)
    const float* convb = (const float*)d_in[2];   // (32,)
    const float* headw = (const float*)d_in[3];   // (32,10)
    const float* headb = (const float*)d_in[4];   // (10,)
    float* out = (float*)d_out;

    k_init<<<16, 256>>>();
    { dim3 g(7,  NIMG); k_stage1<<<g, 256>>>(x); }
    { dim3 g(4,  NIMG); k_stage2<<<g, 256>>>(); }
    { dim3 g(98, B_);   k_convlif<<<g, 256>>>(x, convw, convb); }
    k_final<<<1, 256>>>(headw, headb, out);
}